// round 1
// baseline (speedup 1.0000x reference)
#include <cuda_runtime.h>

#define DIM     128
#define NHEADS  4
#define HD      32
#define MAXN    100000
#define TB      64      // GEMM row-tile
#define XPAD    132     // padded X tile row stride (floats)

// Scratch (allocation-free rule: __device__ globals)
__device__ float g_q[(size_t)MAXN * DIM];
__device__ float g_k[(size_t)MAXN * DIM];
__device__ float g_v[(size_t)MAXN * DIM];
__device__ float g_agg[(size_t)MAXN * DIM];

static const int GEMM_SMEM = (TB * XPAD + DIM * DIM) * 4;  // 99328 B

// ---------- packed fp32x2 helpers (FFMA2 path, sm_100+) ----------
__device__ __forceinline__ unsigned long long pack2(float lo, float hi) {
    unsigned long long r;
    asm("mov.b64 %0, {%1, %2};" : "=l"(r) : "f"(lo), "f"(hi));
    return r;
}
__device__ __forceinline__ void fma2(unsigned long long& d, unsigned long long a,
                                     unsigned long long b) {
    asm("fma.rn.f32x2 %0, %1, %2, %3;" : "=l"(d) : "l"(a), "l"(b), "l"(d));
}
__device__ __forceinline__ float2 unpack2(unsigned long long v) {
    float2 r;
    asm("mov.b64 {%0, %1}, %2;" : "=f"(r.x), "=f"(r.y) : "l"(v));
    return r;
}

// ============================================================================
// Fused Q/K/V projection: one X-tile load, three 128x128 weight GEMMs.
// Block: 256 threads, 64-row tile. Thread microtile: 4 rows x 8 cols
// (held as 4x4 f32x2 accumulators).
// ============================================================================
__global__ void __launch_bounds__(256, 2) qkv_gemm(
    const float* __restrict__ X,
    const float* __restrict__ Wq, const float* __restrict__ bq,
    const float* __restrict__ Wk, const float* __restrict__ bk,
    const float* __restrict__ Wv, const float* __restrict__ bv,
    int N)
{
    extern __shared__ float sm[];
    float* Xs = sm;                // [TB][XPAD]
    float* Ws = sm + TB * XPAD;    // [128][128] (k-major, natural W layout)
    const int tid  = threadIdx.x;
    const int row0 = blockIdx.x * TB;

    // Load X tile (coalesced float4; zero-fill OOB rows)
    {
        const int c4 = tid & 31;
        const int r0 = tid >> 5;
        #pragma unroll
        for (int i = 0; i < TB / 8; i++) {
            int row  = r0 + i * 8;
            int grow = row0 + row;
            float4 v = make_float4(0.f, 0.f, 0.f, 0.f);
            if (grow < N) v = ((const float4*)(X + (size_t)grow * DIM))[c4];
            float* d = Xs + row * XPAD + c4 * 4;
            d[0] = v.x; d[1] = v.y; d[2] = v.z; d[3] = v.w;
        }
    }

    const float* Wp[3] = {Wq, Wk, Wv};
    const float* bp[3] = {bq, bk, bv};
    float*       Op[3] = {g_q, g_k, g_v};

    const int tx = tid & 15;   // col group: cols [tx*8, tx*8+8)
    const int ty = tid >> 4;   // row group: rows [ty*4, ty*4+4)

    #pragma unroll 1
    for (int w = 0; w < 3; w++) {
        __syncthreads();   // protect Ws reuse (and Xs visibility on w==0)
        {
            const int c4 = tid & 31;
            const int r0 = tid >> 5;
            const float4* src = (const float4*)Wp[w];
            #pragma unroll
            for (int i = 0; i < 16; i++) {
                int k = r0 + i * 8;
                ((float4*)(Ws + k * DIM))[c4] = src[k * 32 + c4];
            }
        }
        __syncthreads();

        unsigned long long acc[4][4];
        {
            const float* bb = bp[w] + tx * 8;
            #pragma unroll
            for (int j = 0; j < 4; j++) {
                unsigned long long bv2 = pack2(bb[2 * j], bb[2 * j + 1]);
                #pragma unroll
                for (int i = 0; i < 4; i++) acc[i][j] = bv2;
            }
        }

        #pragma unroll 4
        for (int k = 0; k < DIM; k++) {
            unsigned long long b2[4];
            const unsigned long long* brow =
                (const unsigned long long*)(Ws + k * DIM + tx * 8);
            #pragma unroll
            for (int j = 0; j < 4; j++) b2[j] = brow[j];
            #pragma unroll
            for (int i = 0; i < 4; i++) {
                float a = Xs[(ty * 4 + i) * XPAD + k];
                unsigned long long a2 = pack2(a, a);
                #pragma unroll
                for (int j = 0; j < 4; j++) fma2(acc[i][j], a2, b2[j]);
            }
        }

        float* O = Op[w];
        #pragma unroll
        for (int i = 0; i < 4; i++) {
            int grow = row0 + ty * 4 + i;
            if (grow < N) {
                float2 p0 = unpack2(acc[i][0]), p1 = unpack2(acc[i][1]);
                float2 p2 = unpack2(acc[i][2]), p3 = unpack2(acc[i][3]);
                float4* dst = (float4*)(O + (size_t)grow * DIM + tx * 8);
                dst[0] = make_float4(p0.x, p0.y, p1.x, p1.y);
                dst[1] = make_float4(p2.x, p2.y, p3.x, p3.y);
            }
        }
    }
}

// ============================================================================
// Output GEMM: out = g_agg @ Wo + bo + nodes (residual fused)
// ============================================================================
__global__ void __launch_bounds__(256, 2) out_gemm(
    const float* __restrict__ Wo, const float* __restrict__ bo,
    const float* __restrict__ nodes, float* __restrict__ out, int N)
{
    extern __shared__ float sm[];
    float* Xs = sm;
    float* Ws = sm + TB * XPAD;
    const int tid  = threadIdx.x;
    const int row0 = blockIdx.x * TB;

    {
        const int c4 = tid & 31;
        const int r0 = tid >> 5;
        #pragma unroll
        for (int i = 0; i < TB / 8; i++) {
            int row  = r0 + i * 8;
            int grow = row0 + row;
            float4 v = make_float4(0.f, 0.f, 0.f, 0.f);
            if (grow < N) v = ((const float4*)(g_agg + (size_t)grow * DIM))[c4];
            float* d = Xs + row * XPAD + c4 * 4;
            d[0] = v.x; d[1] = v.y; d[2] = v.z; d[3] = v.w;
        }
        const float4* src = (const float4*)Wo;
        #pragma unroll
        for (int i = 0; i < 16; i++) {
            int k = r0 + i * 8;
            ((float4*)(Ws + k * DIM))[c4] = src[k * 32 + c4];
        }
    }
    __syncthreads();

    const int tx = tid & 15;
    const int ty = tid >> 4;

    unsigned long long acc[4][4];
    {
        const float* bb = bo + tx * 8;
        #pragma unroll
        for (int j = 0; j < 4; j++) {
            unsigned long long bv2 = pack2(bb[2 * j], bb[2 * j + 1]);
            #pragma unroll
            for (int i = 0; i < 4; i++) acc[i][j] = bv2;
        }
    }

    #pragma unroll 4
    for (int k = 0; k < DIM; k++) {
        unsigned long long b2[4];
        const unsigned long long* brow =
            (const unsigned long long*)(Ws + k * DIM + tx * 8);
        #pragma unroll
        for (int j = 0; j < 4; j++) b2[j] = brow[j];
        #pragma unroll
        for (int i = 0; i < 4; i++) {
            float a = Xs[(ty * 4 + i) * XPAD + k];
            unsigned long long a2 = pack2(a, a);
            #pragma unroll
            for (int j = 0; j < 4; j++) fma2(acc[i][j], a2, b2[j]);
        }
    }

    #pragma unroll
    for (int i = 0; i < 4; i++) {
        int grow = row0 + ty * 4 + i;
        if (grow < N) {
            const float4* res = (const float4*)(nodes + (size_t)grow * DIM + tx * 8);
            float4 r0v = res[0], r1v = res[1];
            float2 p0 = unpack2(acc[i][0]), p1 = unpack2(acc[i][1]);
            float2 p2 = unpack2(acc[i][2]), p3 = unpack2(acc[i][3]);
            float4* dst = (float4*)(out + (size_t)grow * DIM + tx * 8);
            dst[0] = make_float4(p0.x + r0v.x, p0.y + r0v.y, p1.x + r0v.z, p1.y + r0v.w);
            dst[1] = make_float4(p2.x + r1v.x, p2.y + r1v.y, p3.x + r1v.z, p3.y + r1v.w);
        }
    }
}

// ============================================================================
// Edge attention + scatter. One warp per edge; lane owns 4 contiguous dims
// (head = lane>>3). Softmax is over the 4 HEADS (faithful to reference).
// Scatter via red.global.add.v4.f32 (4x fewer L2 atomic ops than scalar).
// ============================================================================
__global__ void edge_attn(const int* __restrict__ senders,
                          const int* __restrict__ receivers, int E)
{
    int gw = (blockIdx.x * blockDim.x + threadIdx.x) >> 5;
    if (gw >= E) return;          // uniform per warp
    const int lane = threadIdx.x & 31;
    const int s = senders[gw];
    const int r = receivers[gw];

    float4 q  = ((const float4*)g_q)[s * 32 + lane];
    float4 kk = ((const float4*)g_k)[r * 32 + lane];
    float p = q.x * kk.x + q.y * kk.y + q.z * kk.z + q.w * kk.w;
    // reduce within each 8-lane head group
    p += __shfl_xor_sync(0xffffffffu, p, 4);
    p += __shfl_xor_sync(0xffffffffu, p, 2);
    p += __shfl_xor_sync(0xffffffffu, p, 1);

    const float inv_sqrt_hd = 0.17677669529663687f;  // 1/sqrt(32)
    float s0 = __shfl_sync(0xffffffffu, p, 0)  * inv_sqrt_hd;
    float s1 = __shfl_sync(0xffffffffu, p, 8)  * inv_sqrt_hd;
    float s2 = __shfl_sync(0xffffffffu, p, 16) * inv_sqrt_hd;
    float s3 = __shfl_sync(0xffffffffu, p, 24) * inv_sqrt_hd;

    float m  = fmaxf(fmaxf(s0, s1), fmaxf(s2, s3));
    float e0 = __expf(s0 - m), e1 = __expf(s1 - m);
    float e2 = __expf(s2 - m), e3 = __expf(s3 - m);
    float inv_sum = 1.0f / (e0 + e1 + e2 + e3);
    float eh = (lane & 16) ? ((lane & 8) ? e3 : e2)
                           : ((lane & 8) ? e1 : e0);
    float attn = eh * inv_sum;

    float4 v = ((const float4*)g_v)[s * 32 + lane];
    float* dst = g_agg + (size_t)r * DIM + lane * 4;
    asm volatile("red.global.add.v4.f32 [%0], {%1, %2, %3, %4};"
                 :: "l"(dst), "f"(v.x * attn), "f"(v.y * attn),
                    "f"(v.z * attn), "f"(v.w * attn)
                 : "memory");
}

__global__ void zero_agg_kernel(int n4) {
    int i = blockIdx.x * blockDim.x + threadIdx.x;
    if (i < n4) ((float4*)g_agg)[i] = make_float4(0.f, 0.f, 0.f, 0.f);
}

// ============================================================================
extern "C" void kernel_launch(void* const* d_in, const int* in_sizes, int n_in,
                              void* d_out, int out_size)
{
    const float* nodes     = (const float*)d_in[0];
    const int*   senders   = (const int*)  d_in[1];
    const int*   receivers = (const int*)  d_in[2];
    const float* Wq = (const float*)d_in[3];
    const float* bq = (const float*)d_in[4];
    const float* Wk = (const float*)d_in[5];
    const float* bk = (const float*)d_in[6];
    const float* Wv = (const float*)d_in[7];
    const float* bv = (const float*)d_in[8];
    const float* Wo = (const float*)d_in[9];
    const float* bo = (const float*)d_in[10];

    int N = in_sizes[0] / DIM;
    int E = in_sizes[1];

    cudaFuncSetAttribute(qkv_gemm, cudaFuncAttributeMaxDynamicSharedMemorySize, GEMM_SMEM);
    cudaFuncSetAttribute(out_gemm, cudaFuncAttributeMaxDynamicSharedMemorySize, GEMM_SMEM);

    int gemm_blocks = (N + TB - 1) / TB;
    int n4 = N * (DIM / 4);

    zero_agg_kernel<<<(n4 + 255) / 256, 256>>>(n4);
    qkv_gemm<<<gemm_blocks, 256, GEMM_SMEM>>>(nodes, Wq, bq, Wk, bk, Wv, bv, N);
    edge_attn<<<(E + 7) / 8, 256>>>(senders, receivers, E);
    out_gemm<<<gemm_blocks, 256, GEMM_SMEM>>>(Wo, bo, nodes, (float*)d_out, N);
}